// round 1
// baseline (speedup 1.0000x reference)
#include <cuda_runtime.h>

#define N_TOTAL   4096
#define NN_NODES  1024
#define NN_MARB   3072
#define NN_EATERS 64
#define EPS_F     1e-6f

// Packed (px, py, mass, pad) for broadcast-friendly inner-loop loads.
__device__ float4 g_pack[N_TOTAL];

__global__ void pack_kernel(const float* __restrict__ pos,
                            const float* __restrict__ mass) {
    int j = blockIdx.x * blockDim.x + threadIdx.x;
    if (j < N_TOTAL) {
        g_pack[j] = make_float4(pos[2 * j], pos[2 * j + 1], mass[j], 0.0f);
    }
}

// Each block: 32 consecutive i-bodies (one per lane, replicated over 8 warps).
// Each warp accumulates a disjoint 512-element slice of j, via 2 shared tiles.
__global__ __launch_bounds__(256, 1)
void nbody_kernel(const float* __restrict__ pos,
                  const float* __restrict__ vel,
                  const float* __restrict__ dtp,
                  float* __restrict__ out) {
    __shared__ float4 sh[2048];           // 32 KB tile
    __shared__ float2 spart[8][32];

    const int tid  = threadIdx.x;
    const int lane = tid & 31;
    const int warp = tid >> 5;
    const int i    = blockIdx.x * 32 + lane;

    const float px = pos[2 * i];
    const float py = pos[2 * i + 1];

    float ax = 0.0f, ay = 0.0f;

    #pragma unroll
    for (int tile = 0; tile < 2; tile++) {
        // Cooperative load of 2048 bodies into shared.
        #pragma unroll
        for (int k = 0; k < 8; k++) {
            sh[k * 256 + tid] = g_pack[tile * 2048 + k * 256 + tid];
        }
        __syncthreads();

        const int base = warp * 256;
        #pragma unroll 8
        for (int jj = 0; jj < 256; jj++) {
            float4 q = sh[base + jj];     // warp-uniform -> LDS broadcast
            float dx = q.x - px;
            float dy = q.y - py;
            float d2 = fmaf(dx, dx, fmaf(dy, dy, EPS_F));
            float w  = rsqrtf(d2);        // (d2+eps)^-0.5
            w = w * w * w * q.z;          // m_j * (d2+eps)^-1.5
            // If the pair is coincident (incl. j==i): dx=dy=0 -> contributes 0,
            // exactly matching the reference's masked inv_d3.
            ax = fmaf(w, dx, ax);
            ay = fmaf(w, dy, ay);
        }
        __syncthreads();
    }

    spart[warp][lane] = make_float2(ax, ay);
    __syncthreads();

    if (warp == 0) {
        float fx = 0.0f, fy = 0.0f;
        #pragma unroll
        for (int w = 0; w < 8; w++) {
            fx += spart[w][lane].x;
            fy += spart[w][lane].y;
        }
        const float dt = dtp[0];
        const float vx = vel[2 * i]     + fx * dt;
        const float vy = vel[2 * i + 1] + fy * dt;
        const float nx = px + vx * dt;
        const float ny = py + vy * dt;
        // state_new = stack([pos_new, vel_new]) : pos block first, then vel.
        out[2 * i]                   = nx;
        out[2 * i + 1]               = ny;
        out[2 * N_TOTAL + 2 * i]     = vx;
        out[2 * N_TOTAL + 2 * i + 1] = vy;
    }
}

__global__ void eaten_kernel(const int* __restrict__ eidx,
                             const float* __restrict__ erad,
                             float* __restrict__ out) {
    __shared__ float ex[NN_EATERS], ey[NN_EATERS], er2[NN_EATERS];
    const int tid = threadIdx.x;
    if (tid < NN_EATERS) {
        int e = eidx[tid];                 // index into nodes (< 1024)
        ex[tid] = out[2 * e];              // pos_new[e].x
        ey[tid] = out[2 * e + 1];
        float r = erad[tid];
        er2[tid] = r * r;
    }
    __syncthreads();

    const int m = blockIdx.x * blockDim.x + tid;   // marble 0..3071
    if (m < NN_MARB) {
        const float mx = out[2 * (NN_NODES + m)];
        const float my = out[2 * (NN_NODES + m) + 1];
        int eaten = 0;
        #pragma unroll
        for (int k = 0; k < NN_EATERS; k++) {
            float dx = mx - ex[k];
            float dy = my - ey[k];
            float d2 = fmaf(dx, dx, dy * dy);
            eaten |= (d2 <= er2[k]);
        }
        out[4 * N_TOTAL + m] = eaten ? 1.0f : 0.0f;
    }
}

extern "C" void kernel_launch(void* const* d_in, const int* in_sizes, int n_in,
                              void* d_out, int out_size) {
    const float* positions  = (const float*)d_in[0];
    const float* velocities = (const float*)d_in[1];
    const float* masses     = (const float*)d_in[2];
    const int*   eater_idx  = (const int*)  d_in[3];
    const float* eater_rad  = (const float*)d_in[4];
    const float* dt         = (const float*)d_in[5];
    float* out = (float*)d_out;

    pack_kernel<<<N_TOTAL / 256, 256>>>(positions, masses);
    nbody_kernel<<<N_TOTAL / 32, 256>>>(positions, velocities, dt, out);
    eaten_kernel<<<(NN_MARB + 255) / 256, 256>>>(eater_idx, eater_rad, out);
}

// round 2
// speedup vs baseline: 1.1213x; 1.1213x over previous
#include <cuda_runtime.h>
#include <cstdint>

#define N_TOTAL   4096
#define NN_NODES  1024
#define NN_MARB   3072
#define NN_EATERS 64
#define EPS_F     1e-6f

#define ADD_F32X2(out, a, b) \
    asm("add.rn.f32x2 %0, %1, %2;" : "=l"(out) : "l"(a), "l"(b))
#define FMA_F32X2(out, a, b, c) \
    asm("fma.rn.f32x2 %0, %1, %2, %3;" : "=l"(out) : "l"(a), "l"(b), "l"(c))
#define PACK_F32X2(out, lo, hi) \
    asm("mov.b64 %0, {%1, %2};" : "=l"(out) : "f"(lo), "f"(hi))
#define UNPACK_F32X2(lo, hi, in) \
    asm("mov.b64 {%0, %1}, %2;" : "=f"(lo), "=f"(hi) : "l"(in))

// Each block: 32 consecutive i-bodies (one per lane, replicated over 8 warps).
// Each warp accumulates a disjoint 512-element slice of j, via 2 shared tiles.
__global__ __launch_bounds__(256, 1)
void nbody_kernel(const float* __restrict__ pos,
                  const float* __restrict__ vel,
                  const float* __restrict__ mass,
                  const float* __restrict__ dtp,
                  float* __restrict__ out) {
    __shared__ uint64_t shxy[2048];     // packed (px, py) per body  (16 KB)
    __shared__ float    shm[2048];      // mass                      (8 KB)
    __shared__ float2   spart[8][32];

    const int tid  = threadIdx.x;
    const int lane = tid & 31;
    const int warp = tid >> 5;
    const int i    = blockIdx.x * 32 + lane;

    const float2 p = ((const float2*)pos)[i];

    // negated i-position, packed; and (eps, 0) constant, packed
    uint64_t negp, eps0;
    PACK_F32X2(negp, -p.x, -p.y);
    {
        uint32_t lo = __float_as_uint(EPS_F);
        eps0 = (uint64_t)lo;            // (eps, 0.0f)
    }

    uint64_t acc;
    PACK_F32X2(acc, 0.0f, 0.0f);

    #pragma unroll
    for (int tile = 0; tile < 2; tile++) {
        // Cooperative load of 2048 bodies straight from global (no pack kernel).
        #pragma unroll
        for (int k = 0; k < 8; k++) {
            const int j  = k * 256 + tid;
            const int gj = tile * 2048 + j;
            float2 q = ((const float2*)pos)[gj];
            uint64_t qp;
            PACK_F32X2(qp, q.x, q.y);
            shxy[j] = qp;
            shm[j]  = mass[gj];
        }
        __syncthreads();

        const int base = warp * 256;
        #pragma unroll 8
        for (int jj = 0; jj < 256; jj++) {
            uint64_t qxy = shxy[base + jj];   // LDS.64, warp-uniform broadcast
            float    qm  = shm [base + jj];   // LDS.32
            uint64_t d, s;
            ADD_F32X2(d, qxy, negp);          // (dx, dy)
            FMA_F32X2(s, d, d, eps0);         // (dx^2+eps, dy^2)
            float slo, shi;
            UNPACK_F32X2(slo, shi, s);
            float d2 = slo + shi;             // dx^2 + dy^2 + eps
            float r  = rsqrtf(d2);            // (d2+eps)^-0.5
            float r2 = r * r;
            float mr = r * qm;
            float w  = r2 * mr;               // m_j * (d2+eps)^-1.5
            // Coincident pair (incl. j==i): d = 0 -> contributes 0, matching
            // the reference's masked inv_d3.
            uint64_t wp;
            PACK_F32X2(wp, w, w);
            FMA_F32X2(acc, wp, d, acc);       // (ax += w*dx, ay += w*dy)
        }
        __syncthreads();
    }

    float ax, ay;
    UNPACK_F32X2(ax, ay, acc);
    spart[warp][lane] = make_float2(ax, ay);
    __syncthreads();

    if (warp == 0) {
        float fx = 0.0f, fy = 0.0f;
        #pragma unroll
        for (int w = 0; w < 8; w++) {
            fx += spart[w][lane].x;
            fy += spart[w][lane].y;
        }
        const float dt = dtp[0];
        const float vx = vel[2 * i]     + fx * dt;
        const float vy = vel[2 * i + 1] + fy * dt;
        const float nx = p.x + vx * dt;
        const float ny = p.y + vy * dt;
        // state_new = stack([pos_new, vel_new]) : pos block first, then vel.
        out[2 * i]                   = nx;
        out[2 * i + 1]               = ny;
        out[2 * N_TOTAL + 2 * i]     = vx;
        out[2 * N_TOTAL + 2 * i + 1] = vy;
    }
}

__global__ void eaten_kernel(const int* __restrict__ eidx,
                             const float* __restrict__ erad,
                             float* __restrict__ out) {
    __shared__ float ex[NN_EATERS], ey[NN_EATERS], er2[NN_EATERS];
    const int tid = threadIdx.x;
    if (tid < NN_EATERS) {
        int e = eidx[tid];                 // index into nodes (< 1024)
        ex[tid] = out[2 * e];              // pos_new[e].x
        ey[tid] = out[2 * e + 1];
        float r = erad[tid];
        er2[tid] = r * r;
    }
    __syncthreads();

    const int m = blockIdx.x * blockDim.x + tid;   // marble 0..3071
    if (m < NN_MARB) {
        const float mx = out[2 * (NN_NODES + m)];
        const float my = out[2 * (NN_NODES + m) + 1];
        int eaten = 0;
        #pragma unroll
        for (int k = 0; k < NN_EATERS; k++) {
            float dx = mx - ex[k];
            float dy = my - ey[k];
            float d2 = fmaf(dx, dx, dy * dy);
            eaten |= (d2 <= er2[k]);
        }
        out[4 * N_TOTAL + m] = eaten ? 1.0f : 0.0f;
    }
}

extern "C" void kernel_launch(void* const* d_in, const int* in_sizes, int n_in,
                              void* d_out, int out_size) {
    const float* positions  = (const float*)d_in[0];
    const float* velocities = (const float*)d_in[1];
    const float* masses     = (const float*)d_in[2];
    const int*   eater_idx  = (const int*)  d_in[3];
    const float* eater_rad  = (const float*)d_in[4];
    const float* dt         = (const float*)d_in[5];
    float* out = (float*)d_out;

    nbody_kernel<<<N_TOTAL / 32, 256>>>(positions, velocities, masses, dt, out);
    eaten_kernel<<<(NN_MARB + 255) / 256, 256>>>(eater_idx, eater_rad, out);
}

// round 3
// speedup vs baseline: 1.1404x; 1.0171x over previous
#include <cuda_runtime.h>
#include <cstdint>

#define N_TOTAL   4096
#define NN_NODES  1024
#define NN_MARB   3072
#define NN_EATERS 64
#define EPS_F     1e-6f

#define ADD_F32X2(out, a, b) \
    asm("add.rn.f32x2 %0, %1, %2;" : "=l"(out) : "l"(a), "l"(b))
#define MUL_F32X2(out, a, b) \
    asm("mul.rn.f32x2 %0, %1, %2;" : "=l"(out) : "l"(a), "l"(b))
#define FMA_F32X2(out, a, b, c) \
    asm("fma.rn.f32x2 %0, %1, %2, %3;" : "=l"(out) : "l"(a), "l"(b), "l"(c))
#define PACK_F32X2(out, lo, hi) \
    asm("mov.b64 %0, {%1, %2};" : "=l"(out) : "f"(lo), "f"(hi))
#define UNPACK_F32X2(lo, hi, in) \
    asm("mov.b64 {%0, %1}, %2;" : "=f"(lo), "=f"(hi) : "l"(in))

// Producer/consumer handshake for fused eaten computation.
__device__ int g_ready = 0;   // incremented by the 32 node blocks
__device__ int g_done  = 0;   // incremented by the 96 marble blocks; last resets

// 128 blocks x 256 threads. Block b owns bodies [b*32, b*32+32) (one per lane,
// replicated across 8 warps). Each warp accumulates a disjoint 512-body slice
// of j via 2 shared tiles of 2048 bodies in cross-body-packed SoA form.
__global__ __launch_bounds__(256, 1)
void nbody_fused_kernel(const float* __restrict__ pos,
                        const float* __restrict__ vel,
                        const float* __restrict__ mass,
                        const int*   __restrict__ eidx,
                        const float* __restrict__ erad,
                        const float* __restrict__ dtp,
                        float* __restrict__ out) {
    __shared__ uint64_t shx[1024];      // (x_{2p}, x_{2p+1})  8 KB
    __shared__ uint64_t shy[1024];      // (y_{2p}, y_{2p+1})  8 KB
    __shared__ uint64_t shm[1024];      // (m_{2p}, m_{2p+1})  8 KB
    __shared__ float2   spart[8][32];
    __shared__ float    s_ex[NN_EATERS], s_ey[NN_EATERS], s_er2[NN_EATERS];
    __shared__ int      s_eidx[NN_EATERS];

    const int tid  = threadIdx.x;
    const int lane = tid & 31;
    const int warp = tid >> 5;
    const int blk  = blockIdx.x;
    const int i    = blk * 32 + lane;
    const bool is_marble_blk = (blk >= 32);

    // Marble blocks: prefetch eater metadata early (radii, indices).
    if (is_marble_blk && tid < NN_EATERS) {
        s_eidx[tid] = eidx[tid];
        float r = erad[tid];
        s_er2[tid] = r * r;
    }

    const float2 p = ((const float2*)pos)[i];

    uint64_t npx2, npy2, eps2;
    PACK_F32X2(npx2, -p.x, -p.x);
    PACK_F32X2(npy2, -p.y, -p.y);
    PACK_F32X2(eps2, EPS_F, EPS_F);

    uint64_t AX, AY;
    PACK_F32X2(AX, 0.0f, 0.0f);
    PACK_F32X2(AY, 0.0f, 0.0f);

    #pragma unroll
    for (int tile = 0; tile < 2; tile++) {
        // Cooperative SoA pack of 2048 bodies (1024 pairs): 4 pairs/thread.
        #pragma unroll
        for (int k = 0; k < 4; k++) {
            const int pj = k * 256 + tid;              // pair index in tile
            const int gp = tile * 1024 + pj;           // global pair index
            float4 v  = ((const float4*)pos)[gp];      // (x0,y0,x1,y1)
            float2 mv = ((const float2*)mass)[gp];
            uint64_t xp, yp, mp;
            PACK_F32X2(xp, v.x, v.z);
            PACK_F32X2(yp, v.y, v.w);
            PACK_F32X2(mp, mv.x, mv.y);
            shx[pj] = xp;  shy[pj] = yp;  shm[pj] = mp;
        }
        __syncthreads();

        const int base = warp * 128;                   // 128 pairs per warp
        #pragma unroll 8
        for (int pp = 0; pp < 128; pp++) {
            uint64_t qx = shx[base + pp];              // LDS.64 broadcast
            uint64_t qy = shy[base + pp];
            uint64_t qm = shm[base + pp];
            uint64_t DX, DY, S, R, R2, W;
            ADD_F32X2(DX, qx, npx2);                   // (dx0, dx1)
            ADD_F32X2(DY, qy, npy2);                   // (dy0, dy1)
            FMA_F32X2(S, DX, DX, eps2);                // dx^2 + eps
            FMA_F32X2(S, DY, DY, S);                   // + dy^2 -> (d2_0, d2_1)
            float s0, s1;
            UNPACK_F32X2(s0, s1, S);
            float r0 = rsqrtf(s0);
            float r1 = rsqrtf(s1);
            PACK_F32X2(R, r0, r1);
            MUL_F32X2(R2, R, R);
            MUL_F32X2(W, R, qm);
            MUL_F32X2(W, W, R2);                       // m_j * (d2+eps)^-1.5
            // Coincident pair (incl. j==i): DX=DY=0 -> contributes 0 exactly,
            // matching the reference's masked inv_d3.
            FMA_F32X2(AX, W, DX, AX);
            FMA_F32X2(AY, W, DY, AY);
        }
        __syncthreads();
    }

    {
        float ax0, ax1, ay0, ay1;
        UNPACK_F32X2(ax0, ax1, AX);
        UNPACK_F32X2(ay0, ay1, AY);
        spart[warp][lane] = make_float2(ax0 + ax1, ay0 + ay1);
    }
    __syncthreads();

    float nx = 0.0f, ny = 0.0f;
    if (warp == 0) {
        float fx = 0.0f, fy = 0.0f;
        #pragma unroll
        for (int w = 0; w < 8; w++) {
            fx += spart[w][lane].x;
            fy += spart[w][lane].y;
        }
        const float dt = dtp[0];
        const float vx = vel[2 * i]     + fx * dt;
        const float vy = vel[2 * i + 1] + fy * dt;
        nx = p.x + vx * dt;
        ny = p.y + vy * dt;
        // state_new = stack([pos_new, vel_new]) : pos block first, then vel.
        out[2 * i]                   = nx;
        out[2 * i + 1]               = ny;
        out[2 * N_TOTAL + 2 * i]     = vx;
        out[2 * N_TOTAL + 2 * i + 1] = vy;
    }

    if (!is_marble_blk) {
        // Node block: publish. Ensure pos_new stores are globally visible
        // before signaling.
        __threadfence();
        __syncthreads();
        if (tid == 0) atomicAdd(&g_ready, 1);
        return;
    }

    // ---- Marble block: fused eaten computation ----
    if (tid == 0) {
        while (*((volatile int*)&g_ready) < 32) { /* node blocks never wait */ }
    }
    __syncthreads();
    __threadfence();

    if (tid < NN_EATERS) {
        int e = s_eidx[tid];                     // node index (< 1024)
        s_ex[tid] = __ldcg(&out[2 * e]);         // L2 read (skip stale L1)
        s_ey[tid] = __ldcg(&out[2 * e + 1]);
    }
    __syncthreads();

    if (warp == 0) {
        int eaten = 0;
        #pragma unroll
        for (int k = 0; k < NN_EATERS; k++) {
            float dx = nx - s_ex[k];
            float dy = ny - s_ey[k];
            float d2 = fmaf(dx, dx, dy * dy);
            eaten |= (d2 <= s_er2[k]);
        }
        const int m = i - NN_NODES;              // marble index 0..3071
        out[4 * N_TOTAL + m] = eaten ? 1.0f : 0.0f;
    }
    __syncthreads();

    // Last marble block resets the handshake for the next graph replay.
    if (tid == 0) {
        int d = atomicAdd(&g_done, 1);
        if (d == 95) {
            g_done  = 0;
            __threadfence();
            g_ready = 0;
        }
    }
}

extern "C" void kernel_launch(void* const* d_in, const int* in_sizes, int n_in,
                              void* d_out, int out_size) {
    const float* positions  = (const float*)d_in[0];
    const float* velocities = (const float*)d_in[1];
    const float* masses     = (const float*)d_in[2];
    const int*   eater_idx  = (const int*)  d_in[3];
    const float* eater_rad  = (const float*)d_in[4];
    const float* dt         = (const float*)d_in[5];
    float* out = (float*)d_out;

    nbody_fused_kernel<<<N_TOTAL / 32, 256>>>(positions, velocities, masses,
                                              eater_idx, eater_rad, dt, out);
}